// round 2
// baseline (speedup 1.0000x reference)
#include <cuda_runtime.h>
#include <cuda_bf16.h>
#include <math.h>

// Problem sizes
#define NB    64
#define NS    256
#define NC    16
#define ND    512
#define N4D   2048
#define NVIS  16384            // NB*NS
#define VOCABI 20000

// Recurrence config
#define NCTA_REC 64
#define UNITS    8             // hidden units per CTA
#define GROWS    32            // gate rows per CTA (UNITS*4)
#define WSTRIDE  260           // u32 stride for a 512-bf16 row (+8 bf16 pad)
#define GSTRIDE  34            // float stride for gates smem rows

// ---------------- device scratch (static globals: no allocation) ----------------
__device__ __nv_bfloat16 g_Xhi[NVIS * ND];
__device__ __nv_bfloat16 g_Xlo[NVIS * ND];
__device__ __nv_bfloat16 g_Wih_hi[N4D * ND];
__device__ __nv_bfloat16 g_Wih_lo[N4D * ND];
__device__ __nv_bfloat16 g_Whh_hi[N4D * ND];
__device__ __nv_bfloat16 g_Whh_lo[N4D * ND];
__device__ float         g_Xg[(size_t)NVIS * N4D];        // 134 MB
__device__ __nv_bfloat16 g_h_hi[2 * NB * ND];             // double buffered
__device__ __nv_bfloat16 g_h_lo[2 * NB * ND];
__device__ float         g_final[NB * ND];
__device__ unsigned      g_arrive;

// ---------------- helpers ----------------
__device__ __forceinline__ void mma_bf16(float* c, const unsigned* a, const unsigned* b) {
    asm volatile(
        "mma.sync.aligned.m16n8k16.row.col.f32.bf16.bf16.f32 "
        "{%0,%1,%2,%3}, {%4,%5,%6,%7}, {%8,%9}, {%0,%1,%2,%3};\n"
        : "+f"(c[0]), "+f"(c[1]), "+f"(c[2]), "+f"(c[3])
        : "r"(a[0]), "r"(a[1]), "r"(a[2]), "r"(a[3]), "r"(b[0]), "r"(b[1]));
}

__device__ __forceinline__ void split_bf16(float v, __nv_bfloat16& hi, __nv_bfloat16& lo) {
    hi = __float2bfloat16_rn(v);
    lo = __float2bfloat16_rn(v - __bfloat162float(hi));
}

__device__ __forceinline__ float sigf(float x) { return 1.f / (1.f + expf(-x)); }

// ---------------- kernel 1: weights -> hi/lo bf16 ----------------
__global__ void prep_weights(const float* __restrict__ wih, const float* __restrict__ whh) {
    int i = blockIdx.x * 256 + threadIdx.x;
    if (i < N4D * ND) {
        split_bf16(wih[i], g_Wih_hi[i], g_Wih_lo[i]);
        split_bf16(whh[i], g_Whh_hi[i], g_Whh_lo[i]);
    }
}

// ---------------- kernel 2: embedding-bag sum -> X (hi/lo bf16) ----------------
__global__ void embed_kernel(const int* __restrict__ seqs, const float* __restrict__ emb) {
    int vis = blockIdx.x;          // 0..16383
    int t   = threadIdx.x;         // 0..127
    const int* s = seqs + vis * NC;
    float a0 = 0.f, a1 = 0.f, a2 = 0.f, a3 = 0.f;
#pragma unroll
    for (int c = 0; c < NC; c++) {
        int idx = s[c];
        if (idx >= VOCABI) continue;          // padding row -> zero
        const float* row = emb + (size_t)idx * ND;
        a0 += row[t];
        a1 += row[t + 128];
        a2 += row[t + 256];
        a3 += row[t + 384];
    }
    int base = vis * ND + t;
    split_bf16(a0, g_Xhi[base],       g_Xlo[base]);
    split_bf16(a1, g_Xhi[base + 128], g_Xlo[base + 128]);
    split_bf16(a2, g_Xhi[base + 256], g_Xlo[base + 256]);
    split_bf16(a3, g_Xhi[base + 384], g_Xlo[base + 384]);
}

// ---------------- kernel 3: input GEMM  Xg = X @ W_ih^T  (fp32 via bf16 hi/lo) ----------------
// CTA tile 64(M) x 64(N), K=512 in 16-steps. 8 warps = 4(m) x 2(n); warp tile 16x32.
__global__ void __launch_bounds__(256) input_gemm() {
    __shared__ __nv_bfloat16 sAh[64 * 24];
    __shared__ __nv_bfloat16 sAl[64 * 24];
    __shared__ __nv_bfloat16 sBh[64 * 24];
    __shared__ __nv_bfloat16 sBl[64 * 24];

    int t = threadIdx.x;
    int w = t >> 5, lane = t & 31;
    int wm = w >> 1, wn = w & 1;
    int g = lane >> 2, q = lane & 3;
    int m0 = blockIdx.y * 64, n0 = blockIdx.x * 64;

    int lrow = t >> 2;            // 0..63
    int lc   = (t & 3) * 4;       // 0,4,8,12

    float acc[4][4];
#pragma unroll
    for (int i = 0; i < 4; i++)
#pragma unroll
        for (int j = 0; j < 4; j++) acc[i][j] = 0.f;

    for (int kt = 0; kt < 32; kt++) {
        int k0 = kt * 16;
        // stage tiles (uint2 = 4 bf16 each)
        ((uint2*)sAh)[lrow * 6 + (lc >> 2)] = *(const uint2*)(g_Xhi    + (size_t)(m0 + lrow) * ND + k0 + lc);
        ((uint2*)sAl)[lrow * 6 + (lc >> 2)] = *(const uint2*)(g_Xlo    + (size_t)(m0 + lrow) * ND + k0 + lc);
        ((uint2*)sBh)[lrow * 6 + (lc >> 2)] = *(const uint2*)(g_Wih_hi + (size_t)(n0 + lrow) * ND + k0 + lc);
        ((uint2*)sBl)[lrow * 6 + (lc >> 2)] = *(const uint2*)(g_Wih_lo + (size_t)(n0 + lrow) * ND + k0 + lc);
        __syncthreads();

        const unsigned* Ah = (const unsigned*)sAh;
        const unsigned* Al = (const unsigned*)sAl;
        const unsigned* Bh = (const unsigned*)sBh;
        const unsigned* Bl = (const unsigned*)sBl;

        int ab = (wm * 16 + g) * 12 + q;
        unsigned ah[4] = { Ah[ab], Ah[ab + 96], Ah[ab + 4], Ah[ab + 100] };
        unsigned al[4] = { Al[ab], Al[ab + 96], Al[ab + 4], Al[ab + 100] };

#pragma unroll
        for (int blk = 0; blk < 4; blk++) {
            int bb = (wn * 32 + blk * 8 + g) * 12 + q;
            unsigned bh[2] = { Bh[bb], Bh[bb + 4] };
            unsigned bl[2] = { Bl[bb], Bl[bb + 4] };
            mma_bf16(acc[blk], ah, bh);
            mma_bf16(acc[blk], ah, bl);
            mma_bf16(acc[blk], al, bh);
        }
        __syncthreads();
    }

#pragma unroll
    for (int blk = 0; blk < 4; blk++) {
        int r0 = m0 + wm * 16 + g;
        int cc = n0 + wn * 32 + blk * 8 + 2 * q;
        *(float2*)(g_Xg + (size_t)r0 * N4D + cc)       = make_float2(acc[blk][0], acc[blk][1]);
        *(float2*)(g_Xg + (size_t)(r0 + 8) * N4D + cc) = make_float2(acc[blk][2], acc[blk][3]);
    }
}

// ---------------- kernel 4: reset state + barrier ----------------
__global__ void reset_kernel() {
    int i = blockIdx.x * 256 + threadIdx.x;
    if (i < NB * ND) {
        g_h_hi[i] = __float2bfloat16(0.f);   // buffer 0 (read at step 0)
        g_h_lo[i] = __float2bfloat16(0.f);
    }
    if (i == 0) g_arrive = 0u;
}

// ---------------- kernel 5: persistent LSTM recurrence ----------------
// 64 CTAs (1 per SM), 256 threads. Each CTA owns 8 units (32 gate rows,
// interleaved order per unit: i,f,g,o). W_hh slice lives in SMEM all 256 steps.
// h double-buffered in GMEM; staged into SMEM each step via __ldcg.
__global__ void __launch_bounds__(256, 1) lstm_rec(const int* __restrict__ lengths) {
    extern __shared__ unsigned smem[];
    unsigned* sWh = smem;                        // GROWS*WSTRIDE
    unsigned* sWl = sWh + GROWS * WSTRIDE;
    unsigned* sHh = sWl + GROWS * WSTRIDE;       // NB*WSTRIDE
    unsigned* sHl = sHh + NB * WSTRIDE;
    float*  sGates = (float*)(sHl + NB * WSTRIDE);   // NB * GSTRIDE

    int t = threadIdx.x, cta = blockIdx.x;
    int w = t >> 5, lane = t & 31;
    int wm = w >> 1, wn = w & 1;
    int g = lane >> 2, q = lane & 3;

    // load W_hh slice into smem (hi/lo). slot s -> unit u=s>>2, gate=s&3.
    const unsigned* Whi = (const unsigned*)g_Whh_hi;
    const unsigned* Wlo = (const unsigned*)g_Whh_lo;
    for (int i = t; i < GROWS * 256; i += 256) {
        int s = i >> 8, kw = i & 255;
        int u = s >> 2, gate = s & 3;
        int grow = gate * ND + cta * UNITS + u;
        sWh[s * WSTRIDE + kw] = Whi[grow * 256 + kw];
        sWl[s * WSTRIDE + kw] = Wlo[grow * 256 + kw];
    }

    // epilogue ownership: thread handles (b0,u0) and (b0+32,u0)
    int b0 = t >> 3, u0 = t & 7;
    int len0 = lengths[b0] - 1;
    int len1 = lengths[b0 + 32] - 1;
    float cst0 = 0.f, cst1 = 0.f;
    int jglob = cta * UNITS + u0;

    const unsigned* Hh = (const unsigned*)g_h_hi;
    const unsigned* Hl = (const unsigned*)g_h_lo;
    __syncthreads();

    for (int step = 0; step < NS; step++) {
        int rd = step & 1;
        int wr = rd ^ 1;
        // ---- stage h (bypass L1: written by other CTAs last step) ----
        {
            const unsigned* hh = Hh + rd * (NB * ND / 2);
            const unsigned* hl = Hl + rd * (NB * ND / 2);
            for (int i = t; i < NB * 256; i += 256) {
                int r = i >> 8, kw = i & 255;
                sHh[r * WSTRIDE + kw] = __ldcg(hh + r * 256 + kw);
                sHl[r * WSTRIDE + kw] = __ldcg(hl + r * 256 + kw);
            }
        }
        __syncthreads();

        // ---- mma: gates_part = h @ Wslice^T  (hi/lo split, fp32 acc) ----
        float acc0[4] = {0.f, 0.f, 0.f, 0.f};
        float acc1[4] = {0.f, 0.f, 0.f, 0.f};
        int arow = (wm * 16 + g) * WSTRIDE;
        int b0w_base = (wn * 16 + g) * WSTRIDE;
#pragma unroll 4
        for (int kc = 0; kc < 32; kc++) {
            int ko = kc * 8 + q;
            unsigned ah[4] = { sHh[arow + ko], sHh[arow + 8 * WSTRIDE + ko],
                               sHh[arow + ko + 4], sHh[arow + 8 * WSTRIDE + ko + 4] };
            unsigned al[4] = { sHl[arow + ko], sHl[arow + 8 * WSTRIDE + ko],
                               sHl[arow + ko + 4], sHl[arow + 8 * WSTRIDE + ko + 4] };
            int b0w = b0w_base + ko;
            unsigned bh0[2] = { sWh[b0w], sWh[b0w + 4] };
            unsigned bl0[2] = { sWl[b0w], sWl[b0w + 4] };
            mma_bf16(acc0, ah, bh0);
            mma_bf16(acc0, ah, bl0);
            mma_bf16(acc0, al, bh0);
            int b1w = b0w + 8 * WSTRIDE;
            unsigned bh1[2] = { sWh[b1w], sWh[b1w + 4] };
            unsigned bl1[2] = { sWl[b1w], sWl[b1w + 4] };
            mma_bf16(acc1, ah, bh1);
            mma_bf16(acc1, ah, bl1);
            mma_bf16(acc1, al, bh1);
        }

        // ---- write raw gates to smem ----
        {
            int r0 = wm * 16 + g;
            int c0 = wn * 16 + 2 * q;
            sGates[r0 * GSTRIDE + c0]           = acc0[0];
            sGates[r0 * GSTRIDE + c0 + 1]       = acc0[1];
            sGates[(r0 + 8) * GSTRIDE + c0]     = acc0[2];
            sGates[(r0 + 8) * GSTRIDE + c0 + 1] = acc0[3];
            int c1 = c0 + 8;
            sGates[r0 * GSTRIDE + c1]           = acc1[0];
            sGates[r0 * GSTRIDE + c1 + 1]       = acc1[1];
            sGates[(r0 + 8) * GSTRIDE + c1]     = acc1[2];
            sGates[(r0 + 8) * GSTRIDE + c1 + 1] = acc1[3];
        }
        __syncthreads();

        // ---- epilogue: add Xg, nonlinearity, update c/h, write h (other buffer) ----
#pragma unroll
        for (int p = 0; p < 2; p++) {
            int b = b0 + p * 32;
            float* gp = sGates + b * GSTRIDE + u0 * 4;
            size_t xbase = ((size_t)b * NS + step) * N4D + jglob;
            float gi = gp[0] + g_Xg[xbase];
            float gf = gp[1] + g_Xg[xbase + 512];
            float gg = gp[2] + g_Xg[xbase + 1024];
            float go = gp[3] + g_Xg[xbase + 1536];
            float iv = sigf(gi);
            float fv = sigf(gf);
            float gv = tanhf(gg);
            float ov = sigf(go);
            float c = fv * (p ? cst1 : cst0) + iv * gv;
            if (p) cst1 = c; else cst0 = c;
            float hv = ov * tanhf(c);
            int hidx = wr * (NB * ND) + b * ND + jglob;
            split_bf16(hv, g_h_hi[hidx], g_h_lo[hidx]);
            if (step == (p ? len1 : len0)) g_final[b * ND + jglob] = hv;
        }
        __threadfence();
        __syncthreads();

        // ---- grid barrier (64 co-resident CTAs) ----
        if (t == 0) {
            atomicAdd(&g_arrive, 1u);
            unsigned target = (unsigned)NCTA_REC * (unsigned)(step + 1);
            volatile unsigned* p = &g_arrive;
            while (*p < target) __nanosleep(64);
        }
        __syncthreads();
    }
}

// ---------------- kernel 6: output projection ----------------
__global__ void final_out(const float* __restrict__ w_out, const float* __restrict__ b_out,
                          float* __restrict__ out) {
    int b = blockIdx.x;
    int t = threadIdx.x;
    int r = t >> 5, lane = t & 31;
    float s = 0.f;
    for (int k = lane; k < ND; k += 32)
        s += g_final[b * ND + k] * w_out[r * ND + k];
#pragma unroll
    for (int off = 16; off; off >>= 1) s += __shfl_down_sync(0xffffffffu, s, off);
    if (lane == 0) out[b * 2 + r] = s + b_out[r];
}

// ---------------- launch ----------------
extern "C" void kernel_launch(void* const* d_in, const int* in_sizes, int n_in,
                              void* d_out, int out_size) {
    const int*   seqs    = (const int*)d_in[0];
    const int*   lengths = (const int*)d_in[1];
    const float* emb     = (const float*)d_in[2];
    const float* wih     = (const float*)d_in[3];
    const float* whh     = (const float*)d_in[4];
    const float* wout    = (const float*)d_in[5];
    const float* bout    = (const float*)d_in[6];
    float* out = (float*)d_out;

    const int rec_smem = (2 * GROWS * WSTRIDE + 2 * NB * WSTRIDE) * 4 + NB * GSTRIDE * 4;
    cudaFuncSetAttribute(lstm_rec, cudaFuncAttributeMaxDynamicSharedMemorySize, rec_smem);

    prep_weights<<<4096, 256>>>(wih, whh);
    embed_kernel<<<NVIS, 128>>>(seqs, emb);
    dim3 gg(N4D / 64, NVIS / 64);
    input_gemm<<<gg, 256>>>();
    reset_kernel<<<128, 256>>>();
    lstm_rec<<<NCTA_REC, 256, rec_smem>>>(lengths);
    final_out<<<NB, 64>>>(wout, bout, out);
}

// round 3
// speedup vs baseline: 2.1311x; 2.1311x over previous
#include <cuda_runtime.h>
#include <cuda_bf16.h>
#include <math.h>

// Problem sizes
#define NB    64
#define NS    256
#define NC    16
#define ND    512
#define N4D   2048
#define NVIS  16384            // NB*NS
#define VOCABI 20000

// Recurrence config
#define NCTA_REC 128
#define UNITS    4             // hidden units per CTA
#define GROWS    16            // gate rows per CTA (UNITS*4)
#define WSTRIDE  260           // u32 stride for a 512-bf16 row (+8 bf16 pad) = 1040 B
#define GSTRIDE  20            // float stride for gates smem rows (16 + pad)

// GEMM config
#define GAST_B   80            // bytes per smem row (32 bf16 + 8 pad)
#define GARR_B   10240         // bytes per array per stage (128 rows * 80)
#define GSTAGE_B 40960         // 4 arrays
// ---------------- device scratch (static globals: no allocation) ----------------
__device__ __nv_bfloat16 g_Xhi[NVIS * ND];
__device__ __nv_bfloat16 g_Xlo[NVIS * ND];
__device__ __nv_bfloat16 g_Wih_hi[N4D * ND];
__device__ __nv_bfloat16 g_Wih_lo[N4D * ND];
__device__ __nv_bfloat16 g_Whh_hi[N4D * ND];
__device__ __nv_bfloat16 g_Whh_lo[N4D * ND];
__device__ float         g_Xg[(size_t)NVIS * N4D];        // 134 MB
__device__ __nv_bfloat16 g_h_hi[2 * NB * ND];             // double buffered
__device__ __nv_bfloat16 g_h_lo[2 * NB * ND];
__device__ float         g_final[NB * ND];
__device__ unsigned      g_arrive;

// ---------------- helpers ----------------
__device__ __forceinline__ void mma_bf16(float* c, const unsigned* a, const unsigned* b) {
    asm volatile(
        "mma.sync.aligned.m16n8k16.row.col.f32.bf16.bf16.f32 "
        "{%0,%1,%2,%3}, {%4,%5,%6,%7}, {%8,%9}, {%0,%1,%2,%3};\n"
        : "+f"(c[0]), "+f"(c[1]), "+f"(c[2]), "+f"(c[3])
        : "r"(a[0]), "r"(a[1]), "r"(a[2]), "r"(a[3]), "r"(b[0]), "r"(b[1]));
}

__device__ __forceinline__ void ldsm4(unsigned* r, unsigned saddr) {
    asm volatile("ldmatrix.sync.aligned.m8n8.x4.shared.b16 {%0,%1,%2,%3}, [%4];"
                 : "=r"(r[0]), "=r"(r[1]), "=r"(r[2]), "=r"(r[3]) : "r"(saddr));
}
__device__ __forceinline__ void ldsm2(unsigned* r, unsigned saddr) {
    asm volatile("ldmatrix.sync.aligned.m8n8.x2.shared.b16 {%0,%1}, [%2];"
                 : "=r"(r[0]), "=r"(r[1]) : "r"(saddr));
}
__device__ __forceinline__ void cp16(unsigned s, const void* g) {
    asm volatile("cp.async.cg.shared.global [%0], [%1], 16;\n" :: "r"(s), "l"(g));
}
__device__ __forceinline__ void cp_commit() {
    asm volatile("cp.async.commit_group;\n" ::: "memory");
}
__device__ __forceinline__ void cp_wait0() {
    asm volatile("cp.async.wait_group 0;\n" ::: "memory");
}

__device__ __forceinline__ void split_bf16(float v, __nv_bfloat16& hi, __nv_bfloat16& lo) {
    hi = __float2bfloat16_rn(v);
    lo = __float2bfloat16_rn(v - __bfloat162float(hi));
}

__device__ __forceinline__ float sigf(float x) { return 1.f / (1.f + expf(-x)); }

// ---------------- kernel 1: weights -> hi/lo bf16 ----------------
__global__ void prep_weights(const float* __restrict__ wih, const float* __restrict__ whh) {
    int i = blockIdx.x * 256 + threadIdx.x;
    if (i < N4D * ND) {
        split_bf16(wih[i], g_Wih_hi[i], g_Wih_lo[i]);
        split_bf16(whh[i], g_Whh_hi[i], g_Whh_lo[i]);
    }
}

// ---------------- kernel 2: embedding-bag sum -> X (hi/lo bf16) ----------------
__global__ void embed_kernel(const int* __restrict__ seqs, const float* __restrict__ emb) {
    int vis = blockIdx.x;          // 0..16383
    int t   = threadIdx.x;         // 0..127
    const int* s = seqs + vis * NC;
    float a0 = 0.f, a1 = 0.f, a2 = 0.f, a3 = 0.f;
#pragma unroll
    for (int c = 0; c < NC; c++) {
        int idx = s[c];
        if (idx >= VOCABI) continue;          // padding row -> zero
        const float* row = emb + (size_t)idx * ND;
        a0 += row[t];
        a1 += row[t + 128];
        a2 += row[t + 256];
        a3 += row[t + 384];
    }
    int base = vis * ND + t;
    split_bf16(a0, g_Xhi[base],       g_Xlo[base]);
    split_bf16(a1, g_Xhi[base + 128], g_Xlo[base + 128]);
    split_bf16(a2, g_Xhi[base + 256], g_Xlo[base + 256]);
    split_bf16(a3, g_Xhi[base + 384], g_Xlo[base + 384]);
}

// ---------------- kernel 3: input GEMM  Xg = X @ W_ih^T ----------------
// CTA tile 128x128, 512 threads = 16 warps (4m x 4n), warp tile 32x32.
// 2-stage cp.async pipeline, K=32 per stage, ldmatrix operand loads.
__global__ void __launch_bounds__(512, 1) input_gemm() {
    extern __shared__ unsigned gsm[];
    unsigned sbase = (unsigned)__cvta_generic_to_shared(gsm);

    int t = threadIdx.x;
    int w = t >> 5, lane = t & 31;
    int wm = w >> 2, wn = w & 3;
    int g = lane >> 2, q = lane & 3;
    int m0 = blockIdx.y * 128, n0 = blockIdx.x * 128;

    int lrow = t >> 2;             // 0..127
    int lch  = t & 3;              // 16B chunk

    const __nv_bfloat16* pAh = g_Xhi    + (size_t)(m0 + lrow) * ND + lch * 8;
    const __nv_bfloat16* pAl = g_Xlo    + (size_t)(m0 + lrow) * ND + lch * 8;
    const __nv_bfloat16* pBh = g_Wih_hi + (size_t)(n0 + lrow) * ND + lch * 8;
    const __nv_bfloat16* pBl = g_Wih_lo + (size_t)(n0 + lrow) * ND + lch * 8;
    unsigned sdst = sbase + lrow * GAST_B + lch * 16;

    float acc[2][4][4];
#pragma unroll
    for (int i = 0; i < 2; i++)
#pragma unroll
        for (int j = 0; j < 4; j++)
#pragma unroll
            for (int k = 0; k < 4; k++) acc[i][j][k] = 0.f;

    // prologue load stage 0
    {
        unsigned d = sdst;
        cp16(d,               pAh);
        cp16(d + GARR_B,      pAl);
        cp16(d + 2 * GARR_B,  pBh);
        cp16(d + 3 * GARR_B,  pBl);
        cp_commit();
    }

    // ldmatrix lane address components
    int arow = wm * 32 + (lane & 15);
    int acol = (lane >> 4) * 16;            // byte offset within k-chunk
    int brow = wn * 32 + (lane & 7) + (lane >> 4) * 8;
    int bcol = ((lane >> 3) & 1) * 16;

    for (int s = 0; s < 16; s++) {
        cp_wait0();
        __syncthreads();
        if (s < 15) {
            unsigned d = sdst + ((s + 1) & 1) * GSTAGE_B;
            const int ko = (s + 1) * 32;
            cp16(d,              pAh + ko);
            cp16(d + GARR_B,     pAl + ko);
            cp16(d + 2 * GARR_B, pBh + ko);
            cp16(d + 3 * GARR_B, pBl + ko);
            cp_commit();
        }
        unsigned base = sbase + (s & 1) * GSTAGE_B;
#pragma unroll
        for (int kk = 0; kk < 2; kk++) {
            unsigned koff = kk * 32;
            unsigned ah[2][4], al[2][4], bh[2][4], bl[2][4];
#pragma unroll
            for (int i = 0; i < 2; i++) {
                unsigned ad = base + (arow + i * 16) * GAST_B + koff + acol;
                ldsm4(ah[i], ad);
                ldsm4(al[i], ad + GARR_B);
            }
#pragma unroll
            for (int j2 = 0; j2 < 2; j2++) {
                unsigned bd = base + 2 * GARR_B + (brow + j2 * 16) * GAST_B + koff + bcol;
                ldsm4(bh[j2], bd);
                ldsm4(bl[j2], bd + GARR_B);
            }
#pragma unroll
            for (int i = 0; i < 2; i++)
#pragma unroll
                for (int j = 0; j < 4; j++) {
                    unsigned bhf[2] = { bh[j >> 1][(j & 1) * 2], bh[j >> 1][(j & 1) * 2 + 1] };
                    unsigned blf[2] = { bl[j >> 1][(j & 1) * 2], bl[j >> 1][(j & 1) * 2 + 1] };
                    mma_bf16(acc[i][j], ah[i], bhf);
                    mma_bf16(acc[i][j], ah[i], blf);
                    mma_bf16(acc[i][j], al[i], bhf);
                }
        }
    }

#pragma unroll
    for (int i = 0; i < 2; i++) {
        int r0 = m0 + wm * 32 + i * 16 + g;
#pragma unroll
        for (int j = 0; j < 4; j++) {
            int cc = n0 + wn * 32 + j * 8 + 2 * q;
            *(float2*)(g_Xg + (size_t)r0 * N4D + cc)       = make_float2(acc[i][j][0], acc[i][j][1]);
            *(float2*)(g_Xg + (size_t)(r0 + 8) * N4D + cc) = make_float2(acc[i][j][2], acc[i][j][3]);
        }
    }
}

// ---------------- kernel 4: reset state + barrier ----------------
__global__ void reset_kernel() {
    int i = blockIdx.x * 256 + threadIdx.x;
    if (i < NB * ND) {
        g_h_hi[i] = __float2bfloat16(0.f);   // buffer 0 (read at step 0)
        g_h_lo[i] = __float2bfloat16(0.f);
    }
    if (i == 0) g_arrive = 0u;
}

// ---------------- kernel 5: persistent LSTM recurrence ----------------
// 128 CTAs (1/SM), 256 threads. Each CTA owns 4 units (16 gate rows; slot
// s = u*4+gate). W_hh slice in SMEM all 256 steps; h double-buffered in GMEM,
// staged each step via uint4 __ldcg; operands via ldmatrix.
__global__ void __launch_bounds__(256, 1) lstm_rec(const int* __restrict__ lengths) {
    extern __shared__ unsigned smem[];
    unsigned* sWh = smem;                          // GROWS*WSTRIDE
    unsigned* sWl = sWh + GROWS * WSTRIDE;
    unsigned* sHh = sWl + GROWS * WSTRIDE;         // NB*WSTRIDE
    unsigned* sHl = sHh + NB * WSTRIDE;
    float*  sG = (float*)(sHl + NB * WSTRIDE);     // NB * GSTRIDE

    unsigned sb = (unsigned)__cvta_generic_to_shared(smem);
    unsigned sWh_b = sb;
    unsigned sHh_b = sb + 2u * GROWS * WSTRIDE * 4u;

    int t = threadIdx.x, cta = blockIdx.x;
    int w = t >> 5, lane = t & 31;
    int wm = w >> 1, wn = w & 1;
    int g = lane >> 2, q = lane & 3;

    // load W_hh slice into smem (hi/lo). slot s: u=s>>2, gate=s&3.
    const unsigned* Whi = (const unsigned*)g_Whh_hi;
    const unsigned* Wlo = (const unsigned*)g_Whh_lo;
    for (int i = t; i < GROWS * 256; i += 256) {
        int s = i >> 8, kw = i & 255;
        int u = s >> 2, gate = s & 3;
        int grow = gate * ND + cta * UNITS + u;
        sWh[s * WSTRIDE + kw] = Whi[grow * 256 + kw];
        sWl[s * WSTRIDE + kw] = Wlo[grow * 256 + kw];
    }

    // epilogue ownership: one (batch, unit) pair per thread
    int bb = t >> 2, uu = t & 3;
    int len0 = lengths[bb] - 1;
    float cst = 0.f;
    int jglob = cta * UNITS + uu;

    const uint4* Hh4 = (const uint4*)g_h_hi;
    const uint4* Hl4 = (const uint4*)g_h_lo;

    // ldmatrix lane addresses
    unsigned aoff = sHh_b + (unsigned)(wm * 16 + (lane & 15)) * (WSTRIDE * 4) + (lane >> 4) * 16;
    unsigned boff = sWh_b + (unsigned)(wn * 8 + (lane & 7)) * (WSTRIDE * 4) + ((lane >> 3) & 1) * 16;
    const unsigned HLO = NB * WSTRIDE * 4;       // byte offset sHh -> sHl
    const unsigned WLO = GROWS * WSTRIDE * 4;    // byte offset sWh -> sWl

    __syncthreads();

    for (int step = 0; step < NS; step++) {
        int rd = step & 1;
        int wr = rd ^ 1;

        // prefetch Xg gate values (independent of h)
        size_t xb = ((size_t)bb * NS + step) * N4D + jglob;
        float x0 = __ldcg(g_Xg + xb);
        float x1 = __ldcg(g_Xg + xb + 512);
        float x2 = __ldcg(g_Xg + xb + 1024);
        float x3 = __ldcg(g_Xg + xb + 1536);

        // ---- stage h (bypass L1; uint4) ----
        {
            const uint4* hh = Hh4 + rd * (NB * ND / 8);
            const uint4* hl = Hl4 + rd * (NB * ND / 8);
#pragma unroll
            for (int i = t; i < 4096; i += 256) {
                int r = i >> 6, c = i & 63;
                *(uint4*)(sHh + r * WSTRIDE + c * 4) = __ldcg(hh + r * 64 + c);
                *(uint4*)(sHl + r * WSTRIDE + c * 4) = __ldcg(hl + r * 64 + c);
            }
        }
        __syncthreads();

        // ---- mma: gates = h @ Wslice^T (hi/lo split, fp32 acc) ----
        float acc[4] = {0.f, 0.f, 0.f, 0.f};
#pragma unroll 8
        for (int kc = 0; kc < 32; kc++) {
            unsigned ah[4], al[4], bh[2], bl[2];
            ldsm4(ah, aoff + kc * 32);
            ldsm4(al, aoff + kc * 32 + HLO);
            ldsm2(bh, boff + kc * 32);
            ldsm2(bl, boff + kc * 32 + WLO);
            mma_bf16(acc, ah, bh);
            mma_bf16(acc, ah, bl);
            mma_bf16(acc, al, bh);
        }

        {
            int r0 = wm * 16 + g, c0 = wn * 8 + 2 * q;
            *(float2*)(sG + r0 * GSTRIDE + c0)       = make_float2(acc[0], acc[1]);
            *(float2*)(sG + (r0 + 8) * GSTRIDE + c0) = make_float2(acc[2], acc[3]);
        }
        __syncthreads();

        // ---- epilogue ----
        {
            const float* gp = sG + bb * GSTRIDE + uu * 4;
            float gi = gp[0] + x0;
            float gf = gp[1] + x1;
            float gg = gp[2] + x2;
            float go = gp[3] + x3;
            float iv = sigf(gi);
            float fv = sigf(gf);
            float gv = tanhf(gg);
            float ov = sigf(go);
            float c = fv * cst + iv * gv;
            cst = c;
            float hv = ov * tanhf(c);
            int hidx = wr * (NB * ND) + bb * ND + jglob;
            split_bf16(hv, g_h_hi[hidx], g_h_lo[hidx]);
            if (step == len0) g_final[bb * ND + jglob] = hv;
        }
        __threadfence();
        __syncthreads();

        // ---- grid barrier (128 co-resident CTAs) ----
        if (t == 0) {
            atomicAdd(&g_arrive, 1u);
            unsigned target = (unsigned)NCTA_REC * (unsigned)(step + 1);
            volatile unsigned* p = &g_arrive;
            while (*p < target) __nanosleep(32);
        }
        __syncthreads();
    }
}

// ---------------- kernel 6: output projection ----------------
__global__ void final_out(const float* __restrict__ w_out, const float* __restrict__ b_out,
                          float* __restrict__ out) {
    int b = blockIdx.x;
    int t = threadIdx.x;
    int r = t >> 5, lane = t & 31;
    float s = 0.f;
    for (int k = lane; k < ND; k += 32)
        s += g_final[b * ND + k] * w_out[r * ND + k];
#pragma unroll
    for (int off = 16; off; off >>= 1) s += __shfl_down_sync(0xffffffffu, s, off);
    if (lane == 0) out[b * 2 + r] = s + b_out[r];
}

// ---------------- launch ----------------
extern "C" void kernel_launch(void* const* d_in, const int* in_sizes, int n_in,
                              void* d_out, int out_size) {
    const int*   seqs    = (const int*)d_in[0];
    const int*   lengths = (const int*)d_in[1];
    const float* emb     = (const float*)d_in[2];
    const float* wih     = (const float*)d_in[3];
    const float* whh     = (const float*)d_in[4];
    const float* wout    = (const float*)d_in[5];
    const float* bout    = (const float*)d_in[6];
    float* out = (float*)d_out;

    const int rec_smem = (2 * GROWS * WSTRIDE + 2 * NB * WSTRIDE) * 4 + NB * GSTRIDE * 4;
    cudaFuncSetAttribute(lstm_rec, cudaFuncAttributeMaxDynamicSharedMemorySize, rec_smem);
    const int gemm_smem = 2 * GSTAGE_B;
    cudaFuncSetAttribute(input_gemm, cudaFuncAttributeMaxDynamicSharedMemorySize, gemm_smem);

    prep_weights<<<4096, 256>>>(wih, whh);
    embed_kernel<<<NVIS, 128>>>(seqs, emb);
    dim3 gg(N4D / 128, NVIS / 128);
    input_gemm<<<gg, 512, gemm_smem>>>();
    reset_kernel<<<128, 256>>>();
    lstm_rec<<<NCTA_REC, 256, rec_smem>>>(lengths);
    final_out<<<NB, 64>>>(wout, bout, out);
}

// round 4
// speedup vs baseline: 2.2076x; 1.0359x over previous
#include <cuda_runtime.h>
#include <cuda_bf16.h>
#include <math.h>

// Problem sizes
#define NB    64
#define NS    256
#define NC    16
#define ND    512
#define N4D   2048
#define NVIS  16384            // NB*NS
#define VOCABI 20000

// Recurrence config
#define NCTA_REC 128
#define UNITS    4             // hidden units per CTA
#define GROWS    16            // gate rows per CTA (UNITS*4)
#define WSTRIDE  260           // u32 stride for a 512-bf16 row (+8 bf16 pad) = 1040 B
#define GSTRIDE  20            // float stride for gates smem rows (16 + pad)

// GEMM config
#define GAST_B   80            // bytes per smem row (32 bf16 + 8 pad)
#define GARR_B   10240         // bytes per array per stage (128 rows * 80)
#define GSTAGE_B 40960         // 4 arrays
#define GNSTAGE  3

// ---------------- device scratch (static globals: no allocation) ----------------
__device__ __nv_bfloat16 g_Xhi[NVIS * ND];
__device__ __nv_bfloat16 g_Xlo[NVIS * ND];
__device__ __nv_bfloat16 g_Wih_hi[N4D * ND];
__device__ __nv_bfloat16 g_Wih_lo[N4D * ND];
__device__ __nv_bfloat16 g_Whh_hi[N4D * ND];
__device__ __nv_bfloat16 g_Whh_lo[N4D * ND];
__device__ float         g_Xg[(size_t)NVIS * N4D];        // 134 MB
__device__ __nv_bfloat16 g_h_hi[2 * NB * ND];             // double buffered
__device__ __nv_bfloat16 g_h_lo[2 * NB * ND];
__device__ float         g_final[NB * ND];
__device__ unsigned      g_arrive;

// ---------------- helpers ----------------
__device__ __forceinline__ void mma_bf16(float* c, const unsigned* a, const unsigned* b) {
    asm volatile(
        "mma.sync.aligned.m16n8k16.row.col.f32.bf16.bf16.f32 "
        "{%0,%1,%2,%3}, {%4,%5,%6,%7}, {%8,%9}, {%0,%1,%2,%3};\n"
        : "+f"(c[0]), "+f"(c[1]), "+f"(c[2]), "+f"(c[3])
        : "r"(a[0]), "r"(a[1]), "r"(a[2]), "r"(a[3]), "r"(b[0]), "r"(b[1]));
}

__device__ __forceinline__ void ldsm4(unsigned* r, unsigned saddr) {
    asm volatile("ldmatrix.sync.aligned.m8n8.x4.shared.b16 {%0,%1,%2,%3}, [%4];"
                 : "=r"(r[0]), "=r"(r[1]), "=r"(r[2]), "=r"(r[3]) : "r"(saddr));
}
__device__ __forceinline__ void ldsm2(unsigned* r, unsigned saddr) {
    asm volatile("ldmatrix.sync.aligned.m8n8.x2.shared.b16 {%0,%1}, [%2];"
                 : "=r"(r[0]), "=r"(r[1]) : "r"(saddr));
}
__device__ __forceinline__ void cp16(unsigned s, const void* g) {
    asm volatile("cp.async.cg.shared.global [%0], [%1], 16;\n" :: "r"(s), "l"(g));
}
__device__ __forceinline__ void cp_commit() {
    asm volatile("cp.async.commit_group;\n" ::: "memory");
}
template<int N> __device__ __forceinline__ void cp_wait() {
    asm volatile("cp.async.wait_group %0;\n" :: "n"(N) : "memory");
}

__device__ __forceinline__ void arrive_release(unsigned* p) {
    asm volatile("red.release.gpu.global.add.u32 [%0], 1;" :: "l"(p) : "memory");
}
__device__ __forceinline__ unsigned ld_acquire(const unsigned* p) {
    unsigned v;
    asm volatile("ld.acquire.gpu.global.u32 %0, [%1];" : "=r"(v) : "l"(p) : "memory");
    return v;
}

__device__ __forceinline__ void split_bf16(float v, __nv_bfloat16& hi, __nv_bfloat16& lo) {
    hi = __float2bfloat16_rn(v);
    lo = __float2bfloat16_rn(v - __bfloat162float(hi));
}

__device__ __forceinline__ float sigf(float x) { return 1.f / (1.f + expf(-x)); }

// ---------------- kernel 1: weights -> hi/lo bf16 ----------------
__global__ void prep_weights(const float* __restrict__ wih, const float* __restrict__ whh) {
    int i = blockIdx.x * 256 + threadIdx.x;
    if (i < N4D * ND) {
        split_bf16(wih[i], g_Wih_hi[i], g_Wih_lo[i]);
        split_bf16(whh[i], g_Whh_hi[i], g_Whh_lo[i]);
    }
}

// ---------------- kernel 2: embedding-bag sum -> X (hi/lo bf16) ----------------
__global__ void embed_kernel(const int* __restrict__ seqs, const float* __restrict__ emb) {
    int vis = blockIdx.x;          // 0..16383
    int t   = threadIdx.x;         // 0..127
    const int* s = seqs + vis * NC;
    float a0 = 0.f, a1 = 0.f, a2 = 0.f, a3 = 0.f;
#pragma unroll
    for (int c = 0; c < NC; c++) {
        int idx = s[c];
        if (idx >= VOCABI) continue;          // padding row -> zero
        const float* row = emb + (size_t)idx * ND;
        a0 += row[t];
        a1 += row[t + 128];
        a2 += row[t + 256];
        a3 += row[t + 384];
    }
    int base = vis * ND + t;
    split_bf16(a0, g_Xhi[base],       g_Xlo[base]);
    split_bf16(a1, g_Xhi[base + 128], g_Xlo[base + 128]);
    split_bf16(a2, g_Xhi[base + 256], g_Xlo[base + 256]);
    split_bf16(a3, g_Xhi[base + 384], g_Xlo[base + 384]);
}

// ---------------- kernel 3: input GEMM  Xg = X @ W_ih^T ----------------
// CTA tile 128x128, 512 threads = 16 warps (4m x 4n), warp tile 32x32.
// 3-stage cp.async pipeline, K=32 per stage, ldmatrix operand loads.
__global__ void __launch_bounds__(512, 1) input_gemm() {
    extern __shared__ unsigned gsm[];
    unsigned sbase = (unsigned)__cvta_generic_to_shared(gsm);

    int t = threadIdx.x;
    int w = t >> 5, lane = t & 31;
    int wm = w >> 2, wn = w & 3;
    int g = lane >> 2, q = lane & 3;
    int m0 = blockIdx.y * 128, n0 = blockIdx.x * 128;

    int lrow = t >> 2;             // 0..127
    int lch  = t & 3;              // 16B chunk

    const __nv_bfloat16* pAh = g_Xhi    + (size_t)(m0 + lrow) * ND + lch * 8;
    const __nv_bfloat16* pAl = g_Xlo    + (size_t)(m0 + lrow) * ND + lch * 8;
    const __nv_bfloat16* pBh = g_Wih_hi + (size_t)(n0 + lrow) * ND + lch * 8;
    const __nv_bfloat16* pBl = g_Wih_lo + (size_t)(n0 + lrow) * ND + lch * 8;
    unsigned sdst = sbase + lrow * GAST_B + lch * 16;

    float acc[2][4][4];
#pragma unroll
    for (int i = 0; i < 2; i++)
#pragma unroll
        for (int j = 0; j < 4; j++)
#pragma unroll
            for (int k = 0; k < 4; k++) acc[i][j][k] = 0.f;

    // prologue: stage 0 and 1
#pragma unroll
    for (int ps = 0; ps < 2; ps++) {
        unsigned d = sdst + ps * GSTAGE_B;
        const int ko = ps * 32;
        cp16(d,              pAh + ko);
        cp16(d + GARR_B,     pAl + ko);
        cp16(d + 2 * GARR_B, pBh + ko);
        cp16(d + 3 * GARR_B, pBl + ko);
        cp_commit();
    }

    // ldmatrix lane address components
    int arow = wm * 32 + (lane & 15);
    int acol = (lane >> 4) * 16;            // byte offset within k-chunk
    int brow = wn * 32 + (lane & 7) + (lane >> 4) * 8;
    int bcol = ((lane >> 3) & 1) * 16;

    int buf = 0;                   // = s % 3
    int nbuf = 2;                  // = (s+2) % 3
    for (int s = 0; s < 16; s++) {
        cp_wait<1>();              // group s complete (s+1 may pend)
        __syncthreads();           // all threads done reading buf (s-1)%3
        if (s + 2 < 16) {
            unsigned d = sdst + nbuf * GSTAGE_B;
            const int ko = (s + 2) * 32;
            cp16(d,              pAh + ko);
            cp16(d + GARR_B,     pAl + ko);
            cp16(d + 2 * GARR_B, pBh + ko);
            cp16(d + 3 * GARR_B, pBl + ko);
            cp_commit();
        }
        unsigned base = sbase + buf * GSTAGE_B;
#pragma unroll
        for (int kk = 0; kk < 2; kk++) {
            unsigned koff = kk * 32;
            unsigned ah[2][4], al[2][4], bh[2][4], bl[2][4];
#pragma unroll
            for (int i = 0; i < 2; i++) {
                unsigned ad = base + (arow + i * 16) * GAST_B + koff + acol;
                ldsm4(ah[i], ad);
                ldsm4(al[i], ad + GARR_B);
            }
#pragma unroll
            for (int j2 = 0; j2 < 2; j2++) {
                unsigned bd = base + 2 * GARR_B + (brow + j2 * 16) * GAST_B + koff + bcol;
                ldsm4(bh[j2], bd);
                ldsm4(bl[j2], bd + GARR_B);
            }
#pragma unroll
            for (int i = 0; i < 2; i++)
#pragma unroll
                for (int j = 0; j < 4; j++) {
                    unsigned bhf[2] = { bh[j >> 1][(j & 1) * 2], bh[j >> 1][(j & 1) * 2 + 1] };
                    unsigned blf[2] = { bl[j >> 1][(j & 1) * 2], bl[j >> 1][(j & 1) * 2 + 1] };
                    mma_bf16(acc[i][j], ah[i], bhf);
                    mma_bf16(acc[i][j], ah[i], blf);
                    mma_bf16(acc[i][j], al[i], bhf);
                }
        }
        buf = (buf == 2) ? 0 : buf + 1;
        nbuf = (nbuf == 2) ? 0 : nbuf + 1;
    }

#pragma unroll
    for (int i = 0; i < 2; i++) {
        int r0 = m0 + wm * 32 + i * 16 + g;
#pragma unroll
        for (int j = 0; j < 4; j++) {
            int cc = n0 + wn * 32 + j * 8 + 2 * q;
            *(float2*)(g_Xg + (size_t)r0 * N4D + cc)       = make_float2(acc[i][j][0], acc[i][j][1]);
            *(float2*)(g_Xg + (size_t)(r0 + 8) * N4D + cc) = make_float2(acc[i][j][2], acc[i][j][3]);
        }
    }
}

// ---------------- kernel 4: reset state + barrier ----------------
__global__ void reset_kernel() {
    int i = blockIdx.x * 256 + threadIdx.x;
    if (i < NB * ND) {
        g_h_hi[i] = __float2bfloat16(0.f);   // buffer 0 (read at step 0)
        g_h_lo[i] = __float2bfloat16(0.f);
    }
    if (i == 0) g_arrive = 0u;
}

// ---------------- kernel 5: persistent LSTM recurrence ----------------
// 128 CTAs (1/SM), 256 threads. Each CTA owns 4 units (16 gate rows; slot
// s = u*4+gate). W_hh slice in SMEM all 256 steps; h double-buffered in GMEM.
// h staged each step via cp.async in 4 K-chunks, overlapped with the mma.
__global__ void __launch_bounds__(256, 1) lstm_rec(const int* __restrict__ lengths) {
    extern __shared__ unsigned smem[];
    unsigned* sWh = smem;                          // GROWS*WSTRIDE
    unsigned* sWl = sWh + GROWS * WSTRIDE;
    unsigned* sHh = sWl + GROWS * WSTRIDE;         // NB*WSTRIDE
    unsigned* sHl = sHh + NB * WSTRIDE;
    float*  sG = (float*)(sHl + NB * WSTRIDE);     // NB * GSTRIDE

    unsigned sb = (unsigned)__cvta_generic_to_shared(smem);
    unsigned sWh_b = sb;
    unsigned sHh_b = sb + 2u * GROWS * WSTRIDE * 4u;

    int t = threadIdx.x, cta = blockIdx.x;
    int w = t >> 5, lane = t & 31;
    int wm = w >> 1, wn = w & 1;
    int g = lane >> 2, q = lane & 3;

    // load W_hh slice into smem (hi/lo). slot s: u=s>>2, gate=s&3.
    const unsigned* Whi = (const unsigned*)g_Whh_hi;
    const unsigned* Wlo = (const unsigned*)g_Whh_lo;
    for (int i = t; i < GROWS * 256; i += 256) {
        int s = i >> 8, kw = i & 255;
        int u = s >> 2, gate = s & 3;
        int grow = gate * ND + cta * UNITS + u;
        sWh[s * WSTRIDE + kw] = Whi[grow * 256 + kw];
        sWl[s * WSTRIDE + kw] = Wlo[grow * 256 + kw];
    }

    // epilogue ownership: one (batch, unit) pair per thread
    int bb = t >> 2, uu = t & 3;
    int len0 = lengths[bb] - 1;
    float cst = 0.f;
    int jglob = cta * UNITS + uu;

    // ldmatrix lane addresses
    unsigned aoff = sHh_b + (unsigned)(wm * 16 + (lane & 15)) * (WSTRIDE * 4) + (lane >> 4) * 16;
    unsigned boff = sWh_b + (unsigned)(wn * 8 + (lane & 7)) * (WSTRIDE * 4) + ((lane >> 3) & 1) * 16;
    const unsigned HLO = NB * WSTRIDE * 4;       // byte offset sHh -> sHl
    const unsigned WLO = GROWS * WSTRIDE * 4;    // byte offset sWh -> sWl

    // staging addressing: per chunk c (128 bf16 of K), per thread 4 segs/array
    int srow = t >> 4;                 // reused below per 16-seg stride
    (void)srow;

    // prefetch Xg for step 0
    size_t xb0 = ((size_t)bb * NS + 0) * N4D + jglob;
    float x0 = __ldcg(g_Xg + xb0);
    float x1 = __ldcg(g_Xg + xb0 + 512);
    float x2 = __ldcg(g_Xg + xb0 + 1024);
    float x3 = __ldcg(g_Xg + xb0 + 1536);

    __syncthreads();

    for (int step = 0; step < NS; step++) {
        int rd = step & 1;
        int wr = rd ^ 1;

        // ---- issue h staging: 4 K-chunks, one commit group each ----
        {
            const char* hh = (const char*)g_h_hi + (size_t)rd * (NB * ND * 2);
            const char* hl = (const char*)g_h_lo + (size_t)rd * (NB * ND * 2);
#pragma unroll
            for (int c = 0; c < 4; c++) {
#pragma unroll
                for (int i = t; i < 1024; i += 256) {
                    int r = i >> 4, sg = i & 15;
                    unsigned dst = sHh_b + (unsigned)r * (WSTRIDE * 4) + c * 256 + sg * 16;
                    size_t src = (size_t)r * 1024 + c * 256 + sg * 16;
                    cp16(dst,       hh + src);
                    cp16(dst + HLO, hl + src);
                }
                cp_commit();
            }
        }

        // ---- mma over 4 chunks, overlapped with staging ----
        float acc[4] = {0.f, 0.f, 0.f, 0.f};
#pragma unroll
        for (int c = 0; c < 4; c++) {
            if (c == 0) cp_wait<3>();
            else if (c == 1) cp_wait<2>();
            else if (c == 2) cp_wait<1>();
            else cp_wait<0>();
            __syncthreads();
#pragma unroll
            for (int j = 0; j < 8; j++) {
                int kc = c * 8 + j;
                unsigned ah[4], al[4], bh[2], bl[2];
                ldsm4(ah, aoff + kc * 32);
                ldsm4(al, aoff + kc * 32 + HLO);
                ldsm2(bh, boff + kc * 32);
                ldsm2(bl, boff + kc * 32 + WLO);
                mma_bf16(acc, ah, bh);
                mma_bf16(acc, ah, bl);
                mma_bf16(acc, al, bh);
            }
        }

        {
            int r0 = wm * 16 + g, c0 = wn * 8 + 2 * q;
            *(float2*)(sG + r0 * GSTRIDE + c0)       = make_float2(acc[0], acc[1]);
            *(float2*)(sG + (r0 + 8) * GSTRIDE + c0) = make_float2(acc[2], acc[3]);
        }
        __syncthreads();

        // ---- epilogue ----
        {
            const float* gp = sG + bb * GSTRIDE + uu * 4;
            float gi = gp[0] + x0;
            float gf = gp[1] + x1;
            float gg = gp[2] + x2;
            float go = gp[3] + x3;
            float iv = sigf(gi);
            float fv = sigf(gf);
            float gv = tanhf(gg);
            float ov = sigf(go);
            float c = fv * cst + iv * gv;
            cst = c;
            float hv = ov * tanhf(c);
            int hidx = wr * (NB * ND) + bb * ND + jglob;
            split_bf16(hv, g_h_hi[hidx], g_h_lo[hidx]);
            if (step == len0) g_final[bb * ND + jglob] = hv;
        }
        __syncthreads();            // all h writes issued (+ sG reads done)

        // ---- arrive (release covers CTA's writes via bar.sync ordering) ----
        if (t == 0) arrive_release(&g_arrive);

        // ---- prefetch next step's Xg while barrier settles ----
        {
            int nstep = (step + 1 < NS) ? step + 1 : 0;
            size_t xb = ((size_t)bb * NS + nstep) * N4D + jglob;
            x0 = __ldcg(g_Xg + xb);
            x1 = __ldcg(g_Xg + xb + 512);
            x2 = __ldcg(g_Xg + xb + 1024);
            x3 = __ldcg(g_Xg + xb + 1536);
        }

        // ---- wait ----
        if (t == 0) {
            unsigned target = (unsigned)NCTA_REC * (unsigned)(step + 1);
            while (ld_acquire(&g_arrive) < target) { }
        }
        __syncthreads();
    }
}

// ---------------- kernel 6: output projection ----------------
__global__ void final_out(const float* __restrict__ w_out, const float* __restrict__ b_out,
                          float* __restrict__ out) {
    int b = blockIdx.x;
    int t = threadIdx.x;
    int r = t >> 5, lane = t & 31;
    float s = 0.f;
    for (int k = lane; k < ND; k += 32)
        s += g_final[b * ND + k] * w_out[r * ND + k];
#pragma unroll
    for (int off = 16; off; off >>= 1) s += __shfl_down_sync(0xffffffffu, s, off);
    if (lane == 0) out[b * 2 + r] = s + b_out[r];
}

// ---------------- launch ----------------
extern "C" void kernel_launch(void* const* d_in, const int* in_sizes, int n_in,
                              void* d_out, int out_size) {
    const int*   seqs    = (const int*)d_in[0];
    const int*   lengths = (const int*)d_in[1];
    const float* emb     = (const float*)d_in[2];
    const float* wih     = (const float*)d_in[3];
    const float* whh     = (const float*)d_in[4];
    const float* wout    = (const float*)d_in[5];
    const float* bout    = (const float*)d_in[6];
    float* out = (float*)d_out;

    const int rec_smem = (2 * GROWS * WSTRIDE + 2 * NB * WSTRIDE) * 4 + NB * GSTRIDE * 4;
    cudaFuncSetAttribute(lstm_rec, cudaFuncAttributeMaxDynamicSharedMemorySize, rec_smem);
    const int gemm_smem = GNSTAGE * GSTAGE_B;
    cudaFuncSetAttribute(input_gemm, cudaFuncAttributeMaxDynamicSharedMemorySize, gemm_smem);

    prep_weights<<<4096, 256>>>(wih, whh);
    embed_kernel<<<NVIS, 128>>>(seqs, emb);
    dim3 gg(N4D / 128, NVIS / 128);
    input_gemm<<<gg, 512, gemm_smem>>>();
    reset_kernel<<<128, 256>>>();
    lstm_rec<<<NCTA_REC, 256, rec_smem>>>(lengths);
    final_out<<<NB, 64>>>(wout, bout, out);
}